// round 10
// baseline (speedup 1.0000x reference)
#include <cuda_runtime.h>

typedef unsigned long long u64;

#define SEQ    1024
#define BATCH  512
#define NT     64
#define CH     8
#define NCHUNK (SEQ / CH)   /* 128 */
#define WPB    4            /* warps (=batches) per block */
#define NBLK   (BATCH / WPB)

__device__ float    g_num[BATCH];
__device__ float    g_den[BATCH];
__device__ unsigned g_cnt;   /* zero-initialized; self-resets each launch */

// ---- packed f32x2 helpers ----
__device__ __forceinline__ u64 fma2(u64 a, u64 b, u64 c) {
    u64 d; asm("fma.rn.f32x2 %0, %1, %2, %3;" : "=l"(d) : "l"(a), "l"(b), "l"(c));
    return d;
}
__device__ __forceinline__ u64 add2(u64 a, u64 b) {
    u64 d; asm("add.rn.f32x2 %0, %1, %2;" : "=l"(d) : "l"(a), "l"(b));
    return d;
}
__device__ __forceinline__ float2 unpack2(u64 a) {
    float2 r; asm("mov.b64 {%0,%1}, %2;" : "=f"(r.x), "=f"(r.y) : "l"(a));
    return r;
}
__device__ __forceinline__ u64 pack2(float x, float y) {
    u64 d; asm("mov.b64 %0, {%1,%2};" : "=l"(d) : "f"(x), "f"(y));
    return d;
}

// ---- cp.async 16B ----
__device__ __forceinline__ void cp16(unsigned dst, const void* src) {
    asm volatile("cp.async.ca.shared.global [%0], [%1], 16;"
                 :: "r"(dst), "l"(src));
}
__device__ __forceinline__ void cp_commit() {
    asm volatile("cp.async.commit_group;");
}
template <int N> __device__ __forceinline__ void cp_wait() {
    asm volatile("cp.async.wait_group %0;" :: "n"(N));
}

// ---------------------------------------------------------------------------
// Fused kernel: one WARP per batch. Lane j owns columns j and j+32.
// Alpha interleaved in smem (slot 2j = col j, slot 2j+1 = col j+32; STS.64
// writeback, LDS.128 broadcast reads). Raw emissions staged chunk-ahead via
// cp.async (no registers); expf folded into each step (2 MUFU, interleaved
// with the FFMA2 stream). Fused gold-path numerator + last-block reduction.
// ---------------------------------------------------------------------------
__global__ __launch_bounds__(128, 1) void fused_kernel(
    const float* __restrict__ em,
    const void* __restrict__ tags_raw,
    const int* __restrict__ mask,
    const float* __restrict__ startT,
    const float* __restrict__ endT,
    const float* __restrict__ trans,
    float* __restrict__ out)
{
    const int w = threadIdx.x >> 5;   // warp in block: 0..3
    const int j = threadIdx.x & 31;   // lane
    const int b = blockIdx.x * WPB + w;

    // ---- tags dtype detect (jax x64 -> int64, default -> int32) ----
    const int*       tags32 = (const int*)tags_raw;
    const long long* tags64 = (const long long*)tags_raw;
    unsigned nz = __ballot_sync(0xffffffffu, tags32[2 * j + 1] != 0);
    const int is64 = (nz == 0);

    // ---- E pairs matching interleaved alpha slots (pair i = rows i, i+32) --
    u64 EPa[32], EPb[32];
    #pragma unroll
    for (int i = 0; i < 32; i++) {
        EPa[i] = pack2(__expf(trans[i * NT + j]),
                       __expf(trans[(i + 32) * NT + j]));
        EPb[i] = pack2(__expf(trans[i * NT + j + 32]),
                       __expf(trans[(i + 32) * NT + j + 32]));
    }

    __shared__ __align__(16) float a_s[WPB][2][NT];
    __shared__ __align__(16) float eraw[WPB][2][CH][NT];
    __shared__ short stags[WPB][SEQ];
    __shared__ __align__(8) char smask[WPB][SEQ];

    // ---- preload tags + mask columns ----
    int mcnt = 0;
    #pragma unroll
    for (int t0 = 0; t0 < SEQ; t0 += 32) {
        int t  = t0 + j;
        int mv = mask[t * BATCH + b];
        smask[w][t] = (char)mv;
        mcnt += mv;
        size_t idx = (size_t)t * BATCH + b;
        stags[w][t] = (short)(is64 ? (int)tags64[idx] : tags32[idx]);
    }

    // cp.async lane mapping for one chunk (8 rows x 256B = 4 x 16B per lane)
    const int lrow = j >> 4;          // 0..1 (row within wave-pair)
    const int loff = (j & 15) * 4;    // float offset within row

    // ---- stage chunk 0 into buffer 0 ----
    {
        #pragma unroll
        for (int i = 0; i < 4; i++) {
            int c = i * 2 + lrow;
            unsigned dst = (unsigned)__cvta_generic_to_shared(&eraw[w][0][c][loff]);
            cp16(dst, em + ((size_t)c * BATCH + b) * NT + loff);
        }
        cp_commit();
        cp_wait<0>();
        __syncwarp();
    }

    // alpha0 (interleaved write: one float2)
    float a_pa = __expf(startT[j])      * __expf(eraw[w][0][0][j]);
    float a_pb = __expf(startT[j + 32]) * __expf(eraw[w][0][0][j + 32]);
    *(float2*)&a_s[w][0][2 * j] = make_float2(a_pa, a_pb);
    __syncwarp();

    float logacc = 0.f;
    float rs     = 1.0f;
    int   p      = 0;

    // numerator pipeline state (slice t = k*32 + j, valid for k < 32)
    float score = 0.f;
    float tv_p = 0.f, ev_p = 0.f;
    int   pm_p = 0;

    for (int k = 0; k < NCHUNK; k++) {
        const int buf = k & 1;

        // stage chunk k+1 into buf^1; ensure chunk k's group is complete
        if (k + 1 < NCHUNK) {
            const size_t base = (size_t)(k + 1) * CH;
            #pragma unroll
            for (int i = 0; i < 4; i++) {
                int c = i * 2 + lrow;
                unsigned dst = (unsigned)__cvta_generic_to_shared(&eraw[w][buf ^ 1][c][loff]);
                cp16(dst, em + ((base + c) * BATCH + b) * NT + loff);
            }
            cp_commit();
            cp_wait<1>();
        } else {
            cp_wait<0>();
        }
        __syncwarp();

        // mask bytes for this chunk: one LDS.64
        const u64 mword = *(const u64*)&smask[w][k * CH];

        // numerator: consume last chunk's gathers, issue this chunk's
        if (k >= 1 && k <= 32)
            score += pm_p ? (tv_p + ev_p) : 0.f;
        if (k < 32) {
            int t   = k * 32 + j;
            int cur = stags[w][t];
            if (t == 0) {
                tv_p = startT[cur];
                ev_p = em[(size_t)b * NT + cur];
                pm_p = 1;
            } else {
                pm_p = smask[w][t];
                tv_p = trans[stags[w][t - 1] * NT + cur];
                ev_p = em[((size_t)t * BATCH + b) * NT + cur];
            }
        }

        const int c0 = (k == 0) ? 1 : 0;
        #pragma unroll
        for (int c = 0; c < CH; c++) {
            if (c < c0) continue;

            const int mc = (int)((mword >> (8 * c)) & 0xff);

            // emission exp for this step (issued early; overlaps the dot)
            float ea = __expf(eraw[w][buf][c][j]);
            float eb = __expf(eraw[w][buf][c][j + 32]);

            const ulonglong2* ap = (const ulonglong2*)a_s[w][p];
            u64 aA[4] = {0ull, 0ull, 0ull, 0ull};
            u64 aB[4] = {0ull, 0ull, 0ull, 0ull};
            #pragma unroll
            for (int q = 0; q < 16; q++) {          // 16 x LDS.128 broadcast
                ulonglong2 v = ap[q];
                const int r = 2 * q;
                aA[r & 3]       = fma2(v.x, EPa[r],     aA[r & 3]);
                aA[(r + 1) & 3] = fma2(v.y, EPa[r + 1], aA[(r + 1) & 3]);
                aB[r & 3]       = fma2(v.x, EPb[r],     aB[r & 3]);
                aB[(r + 1) & 3] = fma2(v.y, EPb[r + 1], aB[(r + 1) & 3]);
            }
            float2 fA = unpack2(add2(add2(aA[0], aA[1]), add2(aA[2], aA[3])));
            float2 fB = unpack2(add2(add2(aB[0], aB[1]), add2(aB[2], aB[3])));
            float dotA = fA.x + fA.y;
            float dotB = fB.x + fB.y;

            float v_a = mc ? dotA * (ea * rs) : a_pa * rs;
            float v_b = mc ? dotB * (eb * rs) : a_pb * rs;

            *(float2*)&a_s[w][p ^ 1][2 * j] = make_float2(v_a, v_b);
            a_pa = v_a;
            a_pb = v_b;
            __syncwarp();
            p ^= 1;

            if (c == 0) {   // t % 8 == 0 renorm (k>=1; k==0 starts at c=1)
                const ulonglong2* wp2 = (const ulonglong2*)a_s[w][p];
                u64 s0 = 0ull, s1 = 0ull;
                #pragma unroll
                for (int q = 0; q < 16; q += 2) {
                    ulonglong2 w0 = wp2[q];
                    ulonglong2 w1 = wp2[q + 1];
                    s0 = add2(s0, add2(w0.x, w0.y));
                    s1 = add2(s1, add2(w1.x, w1.y));
                }
                float2 f = unpack2(add2(s0, s1));
                float s  = f.x + f.y;
                rs = __fdividef(1.0f, s);      // consumed next step
                logacc += __logf(s);
            } else {
                rs = 1.0f;
            }
        }
    }

    // ---- denominator epilogue (warp-local) ----
    float s = a_pa * __expf(endT[j]) + a_pb * __expf(endT[j + 32]);
    #pragma unroll
    for (int o = 16; o; o >>= 1)
        s += __shfl_xor_sync(0xffffffffu, s, o);
    if (j == 0)
        g_den[b] = logacc + __logf(s);

    // ---- numerator epilogue (warp-local) ----
    #pragma unroll
    for (int o = 16; o; o >>= 1) {
        score += __shfl_down_sync(0xffffffffu, score, o);
        mcnt  += __shfl_down_sync(0xffffffffu, mcnt, o);
    }
    if (j == 0)
        g_num[b] = score + endT[stags[w][mcnt - 1]];

    // ---- last-block final reduction (deterministic: fixed sum order) ----
    __threadfence();
    __syncthreads();
    __shared__ int is_last;
    if (threadIdx.x == 0) {
        unsigned prev = atomicAdd(&g_cnt, 1u);
        is_last = (prev == NBLK - 1);
    }
    __syncthreads();
    if (is_last) {
        __threadfence();
        int tid = threadIdx.x;  // 0..127
        float v = 0.f;
        #pragma unroll
        for (int r = 0; r < BATCH / 128; r++) {
            int i = tid + r * 128;
            v += g_num[i] - g_den[i];
        }
        #pragma unroll
        for (int o = 16; o; o >>= 1)
            v += __shfl_down_sync(0xffffffffu, v, o);
        __shared__ float ws[4];
        if ((tid & 31) == 0) ws[tid >> 5] = v;
        __syncthreads();
        if (tid == 0) {
            out[0] = (ws[0] + ws[1]) + (ws[2] + ws[3]);
            g_cnt = 0;   // reset for next graph replay
        }
    }
}

// ---------------------------------------------------------------------------
// inputs (metadata order): emissions f32, tags i64-or-i32, mask i32,
//                          start_transitions f32, end_transitions f32,
//                          transitions f32.  output: f32 scalar.
// ---------------------------------------------------------------------------
extern "C" void kernel_launch(void* const* d_in, const int* in_sizes, int n_in,
                              void* d_out, int out_size)
{
    const float* em     = (const float*)d_in[0];
    const void*  tags   = d_in[1];
    const int*   mask   = (const int*)d_in[2];
    const float* startT = (const float*)d_in[3];
    const float* endT   = (const float*)d_in[4];
    const float* trans  = (const float*)d_in[5];
    float*       out    = (float*)d_out;

    fused_kernel<<<NBLK, 32 * WPB>>>(em, tags, mask, startT, endT, trans, out);
}

// round 11
// speedup vs baseline: 1.1395x; 1.1395x over previous
#include <cuda_runtime.h>

typedef unsigned long long u64;

#define SEQ    1024
#define BATCH  512
#define NT     64
#define CH     8
#define NCHUNK (SEQ / CH)   /* 128 */
#define BPB    4            /* batches per block (each = 2 warps) */
#define NBLK   (BATCH / BPB)  /* 128 blocks x 256 threads */

__device__ float    g_num[BATCH];
__device__ float    g_den[BATCH];
__device__ unsigned g_cnt;   /* zero-initialized; self-resets each launch */

// ---- packed f32x2 helpers ----
__device__ __forceinline__ u64 fma2(u64 a, u64 b, u64 c) {
    u64 d; asm("fma.rn.f32x2 %0, %1, %2, %3;" : "=l"(d) : "l"(a), "l"(b), "l"(c));
    return d;
}
__device__ __forceinline__ u64 add2(u64 a, u64 b) {
    u64 d; asm("add.rn.f32x2 %0, %1, %2;" : "=l"(d) : "l"(a), "l"(b));
    return d;
}
__device__ __forceinline__ float2 unpack2(u64 a) {
    float2 r; asm("mov.b64 {%0,%1}, %2;" : "=f"(r.x), "=f"(r.y) : "l"(a));
    return r;
}
__device__ __forceinline__ u64 pack2(float x, float y) {
    u64 d; asm("mov.b64 %0, {%1,%2};" : "=l"(d) : "f"(x), "f"(y));
    return d;
}
__device__ __forceinline__ void barp(int id) {   // 64-thread named barrier
    asm volatile("bar.sync %0, 64;" :: "r"(id) : "memory");
}

// ---------------------------------------------------------------------------
// Fused kernel: TWO warps per batch. Warp sub (0/1) owns columns
// [sub*32, sub*32+32); lane j owns column col = sub*32 + j (ONE column ->
// E = 32 u64 regs, no spills). Alpha in smem, K-pair interleaved:
// slot 2i = alpha[i], slot 2i+1 = alpha[i+32]  (lane writes slot 2j+sub).
// Per-step sync = named bar.sync over the 64-thread pair. 2 warps/SMSP
// (independent batches) hide each other's latency. Renorm every 8 steps by
// the alpha[0] element (uniform scale; 1 LDS + rcp + logf). Fused gold-path
// numerator (slices split between the two warps) + last-block reduction.
// ---------------------------------------------------------------------------
__global__ __launch_bounds__(256, 1) void fused_kernel(
    const float* __restrict__ em,
    const void* __restrict__ tags_raw,
    const int* __restrict__ mask,
    const float* __restrict__ startT,
    const float* __restrict__ endT,
    const float* __restrict__ trans,
    float* __restrict__ out)
{
    const int tid   = threadIdx.x;
    const int wid   = tid >> 5;
    const int j     = tid & 31;
    const int bp    = wid >> 1;          // batch within block: 0..3
    const int sub   = wid & 1;           // column half
    const int b     = blockIdx.x * BPB + bp;
    const int col   = sub * 32 + j;
    const int barid = 1 + bp;

    // ---- tags dtype detect (jax x64 -> int64, default -> int32) ----
    const int*       tags32 = (const int*)tags_raw;
    const long long* tags64 = (const long long*)tags_raw;
    unsigned nz = __ballot_sync(0xffffffffu, tags32[2 * j + 1] != 0);
    const int is64 = (nz == 0);

    // ---- E column in registers, K-packed pairs (i, i+32): 32 u64 ----
    u64 EP[32];
    #pragma unroll
    for (int i = 0; i < 32; i++)
        EP[i] = pack2(__expf(trans[i * NT + col]),
                      __expf(trans[(i + 32) * NT + col]));

    __shared__ __align__(16) float a_s[BPB][2][NT];
    __shared__ short stags[BPB][SEQ];
    __shared__ __align__(8) char smask[BPB][SEQ];
    __shared__ float redf[BPB][2];
    __shared__ float redd[BPB][2];
    __shared__ int   redi[BPB][2];

    // ---- preload tags + mask (64 lanes of the pair cooperate) ----
    int mcnt = 0;
    #pragma unroll
    for (int t0 = 0; t0 < SEQ; t0 += 64) {
        int t  = t0 + col;
        int mv = mask[t * BATCH + b];
        smask[bp][t] = (char)mv;
        mcnt += mv;
        size_t idx = (size_t)t * BATCH + b;
        stags[bp][t] = (short)(is64 ? (int)tags64[idx] : tags32[idx]);
    }

    // ---- stage chunk 0 raw emissions (own column only; 8 regs) ----
    float er[CH];
    #pragma unroll
    for (int c = 0; c < CH; c++)
        er[c] = em[((size_t)c * BATCH + b) * NT + col];

    barp(barid);   // tags/mask visible to both warps

    // alpha0
    float a_prev = __expf(startT[col]) * __expf(er[0]);
    a_s[bp][0][2 * j + sub] = a_prev;
    barp(barid);

    float logacc = 0.f;
    float rs     = 1.0f;
    int   p      = 0;

    // numerator pipeline: slice k (t = k*32 + j·?) owned by warp (k&1)==sub,
    // issued at iteration k, consumed at iteration k+2.
    float score = 0.f;
    float tv = 0.f, ev = 0.f;
    int   pm = 0;

    for (int k = 0; k < NCHUNK; k++) {
        // stage chunk k+1 raw emissions
        float ern[CH];
        if (k + 1 < NCHUNK) {
            const size_t base = (size_t)(k + 1) * CH;
            #pragma unroll
            for (int c = 0; c < CH; c++)
                ern[c] = em[((base + c) * BATCH + b) * NT + col];
        }

        // mask bytes for this chunk: one LDS.64
        const u64 mword = *(const u64*)&smask[bp][k * CH];

        // numerator: this warp handles slices with (k&1)==sub
        if (k < 34 && ((k & 1) == sub)) {
            if (k >= 2)
                score += pm ? (tv + ev) : 0.f;   // consume slice k-2
            if (k < 32) {                         // issue slice k
                int t   = k * 32 + j;
                int cur = stags[bp][t];
                if (t == 0) {
                    tv = startT[cur];
                    ev = em[(size_t)b * NT + cur];
                    pm = 1;
                } else {
                    pm = smask[bp][t];
                    tv = trans[stags[bp][t - 1] * NT + cur];
                    ev = em[((size_t)t * BATCH + b) * NT + cur];
                }
            } else {
                pm = 0;
            }
        }

        const int c0 = (k == 0) ? 1 : 0;
        #pragma unroll
        for (int c = 0; c < CH; c++) {
            if (c < c0) continue;

            const int mc = (int)((mword >> (8 * c)) & 0xff);
            float ea = __expf(er[c]);

            const ulonglong2* ap = (const ulonglong2*)a_s[bp][p];
            u64 a0 = 0ull, a1 = 0ull, a2 = 0ull, a3 = 0ull;
            #pragma unroll
            for (int q = 0; q < 16; q++) {       // 16 x LDS.128 broadcast
                ulonglong2 v = ap[q];
                const int r = 2 * q;
                if ((r & 3) == 0) { a0 = fma2(v.x, EP[r], a0); a1 = fma2(v.y, EP[r + 1], a1); }
                else              { a2 = fma2(v.x, EP[r], a2); a3 = fma2(v.y, EP[r + 1], a3); }
            }
            float2 f = unpack2(add2(add2(a0, a1), add2(a2, a3)));
            float dot = f.x + f.y;

            float v_ = mc ? dot * (ea * rs) : a_prev * rs;

            a_s[bp][p ^ 1][2 * j + sub] = v_;
            a_prev = v_;
            barp(barid);
            p ^= 1;

            if (c == 0) {     // t % 8 == 0 renorm: scale by alpha[0] element
                float az = a_s[bp][p][0];
                rs = __fdividef(1.0f, az);       // consumed next step
                logacc += __logf(az);
            } else {
                rs = 1.0f;
            }
        }

        // roll staged emissions
        if (k + 1 < NCHUNK) {
            #pragma unroll
            for (int c = 0; c < CH; c++)
                er[c] = ern[c];
        }
    }

    // ---- denominator partial (per warp over its 32 columns) ----
    float den = a_prev * __expf(endT[col]);
    #pragma unroll
    for (int o = 16; o; o >>= 1)
        den += __shfl_xor_sync(0xffffffffu, den, o);

    // ---- numerator partials ----
    #pragma unroll
    for (int o = 16; o; o >>= 1) {
        score += __shfl_down_sync(0xffffffffu, score, o);
        mcnt  += __shfl_down_sync(0xffffffffu, mcnt, o);
    }

    if (j == 0) {
        redf[bp][sub] = score;
        redi[bp][sub] = mcnt;
        redd[bp][sub] = den;
    }
    barp(barid);
    if (j == 0 && sub == 0) {
        float sc  = redf[bp][0] + redf[bp][1];
        int   mct = redi[bp][0] + redi[bp][1];
        g_num[b] = sc + endT[stags[bp][mct - 1]];
        g_den[b] = logacc + __logf(redd[bp][0] + redd[bp][1]);
    }

    // ---- last-block final reduction (deterministic: fixed sum order) ----
    __threadfence();
    __syncthreads();
    __shared__ int is_last;
    if (tid == 0) {
        unsigned prev = atomicAdd(&g_cnt, 1u);
        is_last = (prev == NBLK - 1);
    }
    __syncthreads();
    if (is_last) {
        __threadfence();
        float v = 0.f;
        #pragma unroll
        for (int r = 0; r < BATCH / 256; r++) {
            int i = tid + r * 256;
            v += g_num[i] - g_den[i];
        }
        #pragma unroll
        for (int o = 16; o; o >>= 1)
            v += __shfl_down_sync(0xffffffffu, v, o);
        __shared__ float ws[8];
        if ((tid & 31) == 0) ws[tid >> 5] = v;
        __syncthreads();
        if (tid == 0) {
            float t = 0.f;
            #pragma unroll
            for (int i = 0; i < 8; i++) t += ws[i];
            out[0] = t;
            g_cnt = 0;   // reset for next graph replay
        }
    }
}

// ---------------------------------------------------------------------------
// inputs (metadata order): emissions f32, tags i64-or-i32, mask i32,
//                          start_transitions f32, end_transitions f32,
//                          transitions f32.  output: f32 scalar.
// ---------------------------------------------------------------------------
extern "C" void kernel_launch(void* const* d_in, const int* in_sizes, int n_in,
                              void* d_out, int out_size)
{
    const float* em     = (const float*)d_in[0];
    const void*  tags   = d_in[1];
    const int*   mask   = (const int*)d_in[2];
    const float* startT = (const float*)d_in[3];
    const float* endT   = (const float*)d_in[4];
    const float* trans  = (const float*)d_in[5];
    float*       out    = (float*)d_out;

    fused_kernel<<<NBLK, 256>>>(em, tags, mask, startT, endT, trans, out);
}